// round 3
// baseline (speedup 1.0000x reference)
#include <cuda_runtime.h>
#include <math.h>

// ---------------- problem constants ----------------
#define NTOT   16384      // B*NPG
#define BB     32
#define NPG    512
#define DEG    16
#define KCL    64         // clusters per graph
#define ASSIGN 2048       // B*K
#define FIN    128
#define HID    256
#define EMB    256
#define GEMBD  768        // HID+HID+EMB
#define PREDIN 1536       // 2*768

// ---------------- scratch (device globals; no allocs allowed) -------------
__device__ __align__(16) float g_X   [NTOT * 512];        // sage concat input [h|hn]
__device__ __align__(16) float g_G   [NTOT * GEMBD];      // h1|h2|h3
__device__ __align__(16) float g_A12 [NTOT * 512];        // a1|a2
__device__ __align__(16) float g_S   [NTOT * KCL];        // logits -> softmax (in place)
__device__ __align__(16) float g_AS  [NTOT * KCL];
__device__ __align__(16) float g_ST  [BB * KCL * NPG];    // S^T per graph
__device__ __align__(16) float g_Hp  [BB * KCL * GEMBD];  // h_pool
__device__ __align__(16) float g_adj [BB * KCL * KCL];
__device__ __align__(16) float g_asum[BB * KCL];
__device__ __align__(16) float g_Tmp [BB * KCL * GEMBD];  // adj @ h
__device__ __align__(16) float g_XD  [BB * KCL * PREDIN]; // dense concat input
__device__ __align__(16) float g_P   [BB * KCL * GEMBD];  // p1|p2|p3
__device__ __align__(16) float g_Out [BB * PREDIN];
__device__ __align__(16) float g_t1  [BB * HID];

// ---------------- kernels ----------------

// X[n, 0:F] = h[n], X[n, F:2F] = (1/16) * sum_j h[edge_src[16n+j]]
// relies on edge_dst = repeat(arange(N), 16) (sorted, constant degree 16)
__global__ void build_sage_x(const float* __restrict__ h, int ldh, int F,
                             const int* __restrict__ esrc, float* __restrict__ X)
{
    int n = blockIdx.x;
    int f = threadIdx.x;            // blockDim == F
    __shared__ int s[DEG];
    if (f < DEG) s[f] = esrc[n * DEG + f];
    __syncthreads();
    float self = h[(long)n * ldh + f];
    float acc = 0.f;
#pragma unroll
    for (int j = 0; j < DEG; j++) acc += h[(long)s[j] * ldh + f];
    long base = (long)n * (2 * F);
    X[base + f]     = self;
    X[base + F + f] = acc * (1.0f / 16.0f);
}

// AS[n,k] = sum_j S[edge_src[16n+j], k]   (no mean)
__global__ void agg_sum64(const float* __restrict__ S, const int* __restrict__ esrc,
                          float* __restrict__ AS)
{
    int n = blockIdx.x;
    int f = threadIdx.x;            // 64
    __shared__ int s[DEG];
    if (f < DEG) s[f] = esrc[n * DEG + f];
    __syncthreads();
    float acc = 0.f;
#pragma unroll
    for (int j = 0; j < DEG; j++) acc += S[(long)s[j] * KCL + f];
    AS[(long)n * KCL + f] = acc;
}

// generic guarded SGEMM: C = A @ W + bias (opt relu), batched via blockIdx.z
__global__ void sgemm(const float* __restrict__ A, long sA, int lda,
                      const float* __restrict__ W, long sW, int ldw,
                      const float* __restrict__ bias, long sB,
                      float* __restrict__ C, long sC, int ldc,
                      int M, int Nn, int Kk, int relu)
{
    int z = blockIdx.z;
    A += (long)z * sA; W += (long)z * sW; C += (long)z * sC;
    if (bias) bias += (long)z * sB;

    __shared__ float As[8][128];
    __shared__ float Bs[8][128];
    int tid  = threadIdx.x;
    int brow = blockIdx.y * 128, bcol = blockIdx.x * 128;
    int ty = tid >> 4, tx = tid & 15;
    float acc[8][8];
#pragma unroll
    for (int i = 0; i < 8; i++)
#pragma unroll
        for (int j = 0; j < 8; j++) acc[i][j] = 0.f;

    int arow = tid >> 1;           // 0..127
    int acol = (tid & 1) * 4;      // 0 or 4

    for (int k0 = 0; k0 < Kk; k0 += 8) {
        float4 av = make_float4(0.f, 0.f, 0.f, 0.f);
        int gr = brow + arow;
        if (gr < M) av = *reinterpret_cast<const float4*>(A + (long)gr * lda + k0 + acol);
        As[acol + 0][arow] = av.x; As[acol + 1][arow] = av.y;
        As[acol + 2][arow] = av.z; As[acol + 3][arow] = av.w;
#pragma unroll
        for (int i = 0; i < 4; i++) {
            int off = tid + i * 256;
            int wr = off >> 7, wc = off & 127;
            int gc = bcol + wc;
            Bs[wr][wc] = (gc < Nn) ? W[(long)(k0 + wr) * ldw + gc] : 0.f;
        }
        __syncthreads();
#pragma unroll
        for (int kk = 0; kk < 8; kk++) {
            float ra[8], rb[8];
#pragma unroll
            for (int i = 0; i < 8; i++) ra[i] = As[kk][ty * 8 + i];
#pragma unroll
            for (int j = 0; j < 8; j++) rb[j] = Bs[kk][tx * 8 + j];
#pragma unroll
            for (int i = 0; i < 8; i++)
#pragma unroll
                for (int j = 0; j < 8; j++) acc[i][j] = fmaf(ra[i], rb[j], acc[i][j]);
        }
        __syncthreads();
    }
#pragma unroll
    for (int i = 0; i < 8; i++) {
        int r = brow + ty * 8 + i;
        if (r >= M) continue;
#pragma unroll
        for (int j = 0; j < 8; j++) {
            int c = bcol + tx * 8 + j;
            if (c >= Nn) continue;
            float v = acc[i][j] + (bias ? bias[c] : 0.f);
            if (relu) v = fmaxf(v, 0.f);
            C[(long)r * ldc + c] = v;
        }
    }
}

// Fused: S[rows of tile, 64] += relu(X3_tile @ aW3 + ab3) @ pW[512:, local 64]
// X3 = [a2 | mean a2], [N,512]. a3 never materialized in global memory.
// One block per 128-node tile (tiles never cross graphs since NPG=512).
// Dynamic smem: Ts[128*128] + Ws[128*64] + As[8*128] + Bs[8*128] = 104KB.
__global__ void fused_a3_logits(const float* __restrict__ X3,
                                const float* __restrict__ aW3,  // [512,2048]
                                const float* __restrict__ ab3,  // [2048]
                                const float* __restrict__ pW,   // [2560,2048]
                                float* __restrict__ S)          // [N,64] (+=)
{
    extern __shared__ float sm[];
    float* Ts = sm;                  // [t(128)][i(128)]  t-major
    float* Ws = Ts + 128 * 128;      // [t(128)][j(64)]
    float* As = Ws + 128 * 64;       // [k(8)][i(128)]
    float* Bs = As + 8 * 128;        // [k(8)][c(128)]

    int tid = threadIdx.x;           // 256
    int ty = tid >> 4, tx = tid & 15;
    int row0 = blockIdx.x * 128;
    int b = row0 >> 9;
    const float* pW3 = pW + (long)512 * ASSIGN + b * KCL;

    float L[8][4];
#pragma unroll
    for (int i = 0; i < 8; i++)
#pragma unroll
        for (int j = 0; j < 4; j++) L[i][j] = 0.f;

    int arow = tid >> 1;
    int acol = (tid & 1) * 4;

    for (int c = 0; c < ASSIGN; c += 128) {
        // ---- GEMM1: acc = X3_tile[128x512] @ aW3[:, c:c+128] ----
        float acc[8][8];
#pragma unroll
        for (int i = 0; i < 8; i++)
#pragma unroll
            for (int j = 0; j < 8; j++) acc[i][j] = 0.f;

        for (int k0 = 0; k0 < 512; k0 += 8) {
            float4 av = *reinterpret_cast<const float4*>(
                X3 + (long)(row0 + arow) * 512 + k0 + acol);
            As[(acol + 0) * 128 + arow] = av.x;
            As[(acol + 1) * 128 + arow] = av.y;
            As[(acol + 2) * 128 + arow] = av.z;
            As[(acol + 3) * 128 + arow] = av.w;
#pragma unroll
            for (int i = 0; i < 4; i++) {
                int off = tid + i * 256;
                int wr = off >> 7, wc = off & 127;
                Bs[wr * 128 + wc] = aW3[(long)(k0 + wr) * ASSIGN + c + wc];
            }
            __syncthreads();
#pragma unroll
            for (int kk = 0; kk < 8; kk++) {
                float ra[8], rb[8];
#pragma unroll
                for (int i = 0; i < 8; i++) ra[i] = As[kk * 128 + ty * 8 + i];
#pragma unroll
                for (int j = 0; j < 8; j++) rb[j] = Bs[kk * 128 + tx * 8 + j];
#pragma unroll
                for (int i = 0; i < 8; i++)
#pragma unroll
                    for (int j = 0; j < 8; j++) acc[i][j] = fmaf(ra[i], rb[j], acc[i][j]);
            }
            __syncthreads();
        }
        // bias + relu -> Ts (t-major), and stage pW3 chunk -> Ws
#pragma unroll
        for (int jj = 0; jj < 8; jj++) {
            int t = tx * 8 + jj;
            float bb = ab3[c + t];
#pragma unroll
            for (int ii = 0; ii < 8; ii++) {
                Ts[t * 128 + ty * 8 + ii] = fmaxf(acc[ii][jj] + bb, 0.f);
            }
        }
        for (int idx = tid; idx < 128 * 64; idx += 256) {
            int t = idx >> 6, j = idx & 63;
            Ws[idx] = pW3[(long)(c + t) * ASSIGN + j];
        }
        __syncthreads();
        // ---- GEMM2: L += Ts^T-slice @ Ws ----
#pragma unroll 4
        for (int t = 0; t < 128; t++) {
            float rb[4];
#pragma unroll
            for (int j = 0; j < 4; j++) rb[j] = Ws[t * 64 + tx * 4 + j];
            float ra[8];
#pragma unroll
            for (int i = 0; i < 8; i++) ra[i] = Ts[t * 128 + ty * 8 + i];
#pragma unroll
            for (int i = 0; i < 8; i++)
#pragma unroll
                for (int j = 0; j < 4; j++) L[i][j] = fmaf(ra[i], rb[j], L[i][j]);
        }
        __syncthreads();   // protect Ts/Ws before next chunk rewrites
    }
#pragma unroll
    for (int i = 0; i < 8; i++) {
        long r = row0 + ty * 8 + i;
#pragma unroll
        for (int j = 0; j < 4; j++)
            S[r * KCL + tx * 4 + j] += L[i][j];
    }
}

// masked softmax over the local 64 columns (in place)
__global__ void softmax64(float* __restrict__ S)
{
    int n = blockIdx.x, c = threadIdx.x;  // 64 threads
    __shared__ float red[64];
    float v = S[(long)n * KCL + c];
    red[c] = v; __syncthreads();
    for (int s = 32; s > 0; s >>= 1) { if (c < s) red[c] = fmaxf(red[c], red[c + s]); __syncthreads(); }
    float m = red[0]; __syncthreads();
    float e = expf(v - m);
    red[c] = e; __syncthreads();
    for (int s = 32; s > 0; s >>= 1) { if (c < s) red[c] += red[c + s]; __syncthreads(); }
    float sum = red[0];
    S[(long)n * KCL + c] = e / sum;
}

// ST[b,k,n_local] = S[b*512+n_local, k]
__global__ void transS(const float* __restrict__ S, float* __restrict__ ST)
{
    int n = blockIdx.x, k = threadIdx.x;  // 64
    int b = n >> 9, nn = n & 511;
    ST[((long)(b * KCL + k)) * NPG + nn] = S[(long)n * KCL + k];
}

__global__ void adjsum_k(const float* __restrict__ adj, float* __restrict__ asum)
{
    int i = blockIdx.x * blockDim.x + threadIdx.x;
    if (i < BB * KCL) {
        float s = 0.f;
#pragma unroll 8
        for (int j = 0; j < KCL; j++) s += adj[(long)i * KCL + j];
        asum[i] = s + 1e-9f;
    }
}

// XD[i, 0:d] = h[i], XD[i, d:2d] = tmp[i] / asum[i]
__global__ void dense_concat(const float* __restrict__ h, int ldh,
                             const float* __restrict__ tmp, int d,
                             const float* __restrict__ asum, float* __restrict__ XD)
{
    int i = blockIdx.x, t = threadIdx.x;  // blockDim == d
    float inv = 1.0f / asum[i];
    long base = (long)i * (2 * d);
    XD[base + t]     = h[(long)i * ldh + t];
    XD[base + d + t] = tmp[(long)i * d + t] * inv;
}

__global__ void maxpool_k(const float* __restrict__ Xp, int rows, int ld, int d,
                          float* __restrict__ out, int ldo, int off)
{
    int b = blockIdx.x;
    int j = blockIdx.y * blockDim.x + threadIdx.x;
    if (j >= d) return;
    const float* p = Xp + (long)b * rows * ld + j;
    float m = -3.4e38f;
    for (int r = 0; r < rows; r++) m = fmaxf(m, p[(long)r * ld]);
    out[(long)b * ldo + off + j] = m;
}

// ---------------- launch ----------------
extern "C" void kernel_launch(void* const* d_in, const int* in_sizes, int n_in,
                              void* d_out, int out_size)
{
    const float* feat = (const float*)d_in[0];
    const int*   esrc = (const int*)d_in[1];
    // d_in[2] = edge_dst (structure known: repeat(arange(N),16))
    const float *W1 = (const float*)d_in[3],  *b1  = (const float*)d_in[4];
    const float *W2 = (const float*)d_in[5],  *b2  = (const float*)d_in[6];
    const float *W3 = (const float*)d_in[7],  *b3  = (const float*)d_in[8];
    const float *aW1= (const float*)d_in[9],  *ab1 = (const float*)d_in[10];
    const float *aW2= (const float*)d_in[11], *ab2 = (const float*)d_in[12];
    const float *aW3= (const float*)d_in[13], *ab3 = (const float*)d_in[14];
    const float *pW = (const float*)d_in[15], *pb  = (const float*)d_in[16];
    const float *qW1= (const float*)d_in[17], *qb1 = (const float*)d_in[18];
    const float *qW2= (const float*)d_in[19], *qb2 = (const float*)d_in[20];
    const float *qW3= (const float*)d_in[21], *qb3 = (const float*)d_in[22];
    const float *mW1= (const float*)d_in[23], *mb1 = (const float*)d_in[24];
    const float *mW2= (const float*)d_in[25], *mb2 = (const float*)d_in[26];
    float* out = (float*)d_out;

    void *p;
    cudaGetSymbolAddress(&p, g_X);    float* X   = (float*)p;
    cudaGetSymbolAddress(&p, g_G);    float* G   = (float*)p;
    cudaGetSymbolAddress(&p, g_A12);  float* A12 = (float*)p;
    cudaGetSymbolAddress(&p, g_S);    float* S   = (float*)p;
    cudaGetSymbolAddress(&p, g_AS);   float* AS  = (float*)p;
    cudaGetSymbolAddress(&p, g_ST);   float* ST  = (float*)p;
    cudaGetSymbolAddress(&p, g_Hp);   float* Hp  = (float*)p;
    cudaGetSymbolAddress(&p, g_adj);  float* adj = (float*)p;
    cudaGetSymbolAddress(&p, g_asum); float* asum= (float*)p;
    cudaGetSymbolAddress(&p, g_Tmp);  float* Tmp = (float*)p;
    cudaGetSymbolAddress(&p, g_XD);   float* XD  = (float*)p;
    cudaGetSymbolAddress(&p, g_P);    float* P   = (float*)p;
    cudaGetSymbolAddress(&p, g_Out);  float* Out = (float*)p;
    cudaGetSymbolAddress(&p, g_t1);   float* t1  = (float*)p;

    const int FUSED_SMEM = (128 * 128 + 128 * 64 + 8 * 128 + 8 * 128) * 4;  // 104KB
    cudaFuncSetAttribute(fused_a3_logits, cudaFuncAttributeMaxDynamicSharedMemorySize, FUSED_SMEM);

    dim3 blk(256);
    #define GGRID(Nn, M, Z) dim3(((Nn)+127)/128, ((M)+127)/128, (Z))

    // ---- shared first sage input (feat) ----
    build_sage_x<<<NTOT, FIN>>>(feat, FIN, FIN, esrc, X);
    // h1 = relu(X @ W1 + b1) ; a1 = relu(X @ aW1 + ab1)
    sgemm<<<GGRID(HID, NTOT, 1), blk>>>(X, 0, 2*FIN, W1, 0, HID, b1, 0, G,      0, GEMBD, NTOT, HID, 2*FIN, 1);
    sgemm<<<GGRID(HID, NTOT, 1), blk>>>(X, 0, 2*FIN, aW1,0, HID, ab1,0, A12,    0, 512,   NTOT, HID, 2*FIN, 1);
    // h2
    build_sage_x<<<NTOT, HID>>>(G, GEMBD, HID, esrc, X);
    sgemm<<<GGRID(HID, NTOT, 1), blk>>>(X, 0, 2*HID, W2, 0, HID, b2, 0, G+HID,  0, GEMBD, NTOT, HID, 2*HID, 1);
    // a2
    build_sage_x<<<NTOT, HID>>>(A12, 512, HID, esrc, X);
    sgemm<<<GGRID(HID, NTOT, 1), blk>>>(X, 0, 2*HID, aW2,0, HID, ab2,0, A12+HID,0, 512,   NTOT, HID, 2*HID, 1);
    // h3 (no relu)
    build_sage_x<<<NTOT, HID>>>(G+HID, GEMBD, HID, esrc, X);
    sgemm<<<GGRID(EMB, NTOT, 1), blk>>>(X, 0, 2*HID, W3, 0, EMB, b3, 0, G+2*HID,0, GEMBD, NTOT, EMB, 2*HID, 0);

    // ---- logits: [a1|a2] part (batched local-64-column slice of pW) ----
    sgemm<<<GGRID(KCL, NPG, BB), blk>>>(A12, (long)NPG*512, 512,
                                        pW, KCL, ASSIGN, pb, KCL,
                                        S, (long)NPG*KCL, KCL, NPG, KCL, 512, 0);
    // ---- a3 part, fused (a3 never hits DRAM) ----
    build_sage_x<<<NTOT, HID>>>(A12+HID, 512, HID, esrc, X);
    fused_a3_logits<<<NTOT/128, 256, FUSED_SMEM>>>(X, aW3, ab3, pW, S);
    softmax64<<<NTOT, KCL>>>(S);

    // ---- pooling ----
    agg_sum64<<<NTOT, KCL>>>(S, esrc, AS);
    transS<<<NTOT, KCL>>>(S, ST);
    // h_pool[b] = S[b]^T @ G[b]   (64 x 768)
    sgemm<<<GGRID(GEMBD, KCL, BB), blk>>>(ST, (long)KCL*NPG, NPG,
                                          G, (long)NPG*GEMBD, GEMBD, (const float*)0, 0,
                                          Hp, (long)KCL*GEMBD, GEMBD, KCL, GEMBD, NPG, 0);
    // adj[b] = S[b]^T @ AS[b]     (64 x 64)
    sgemm<<<GGRID(KCL, KCL, BB), blk>>>(ST, (long)KCL*NPG, NPG,
                                        AS, (long)NPG*KCL, KCL, (const float*)0, 0,
                                        adj, (long)KCL*KCL, KCL, KCL, KCL, NPG, 0);
    adjsum_k<<<(BB*KCL+255)/256, 256>>>(adj, asum);

    // ---- dense sage layer 1 (input 768 -> 256, relu) ----
    sgemm<<<GGRID(GEMBD, KCL, BB), blk>>>(adj, (long)KCL*KCL, KCL,
                                          Hp, (long)KCL*GEMBD, GEMBD, (const float*)0, 0,
                                          Tmp, (long)KCL*GEMBD, GEMBD, KCL, GEMBD, KCL, 0);
    dense_concat<<<BB*KCL, GEMBD>>>(Hp, GEMBD, Tmp, GEMBD, asum, XD);
    sgemm<<<GGRID(HID, BB*KCL, 1), blk>>>(XD, 0, PREDIN, qW1, 0, HID, qb1, 0, P, 0, GEMBD, BB*KCL, HID, PREDIN, 1);
    // layer 2 (256 -> 256, relu)
    sgemm<<<GGRID(HID, KCL, BB), blk>>>(adj, (long)KCL*KCL, KCL,
                                        P, (long)KCL*GEMBD, GEMBD, (const float*)0, 0,
                                        Tmp, (long)KCL*HID, HID, KCL, HID, KCL, 0);
    dense_concat<<<BB*KCL, HID>>>(P, GEMBD, Tmp, HID, asum, XD);
    sgemm<<<GGRID(HID, BB*KCL, 1), blk>>>(XD, 0, 2*HID, qW2, 0, HID, qb2, 0, P+HID, 0, GEMBD, BB*KCL, HID, 2*HID, 1);
    // layer 3 (256 -> 256, no relu)
    sgemm<<<GGRID(HID, KCL, BB), blk>>>(adj, (long)KCL*KCL, KCL,
                                        P+HID, (long)KCL*GEMBD, GEMBD, (const float*)0, 0,
                                        Tmp, (long)KCL*HID, HID, KCL, HID, KCL, 0);
    dense_concat<<<BB*KCL, HID>>>(P+HID, GEMBD, Tmp, HID, asum, XD);
    sgemm<<<GGRID(HID, BB*KCL, 1), blk>>>(XD, 0, 2*HID, qW3, 0, HID, qb3, 0, P+2*HID, 0, GEMBD, BB*KCL, HID, 2*HID, 0);

    // ---- readouts ----
    maxpool_k<<<dim3(BB, (GEMBD+255)/256), 256>>>(G, NPG, GEMBD, GEMBD, Out, PREDIN, 0);
    maxpool_k<<<dim3(BB, (GEMBD+255)/256), 256>>>(P, KCL, GEMBD, GEMBD, Out, PREDIN, GEMBD);

    // ---- pred MLP ----
    sgemm<<<GGRID(HID, BB, 1), blk>>>(Out, 0, PREDIN, mW1, 0, HID, mb1, 0, t1, 0, HID, BB, HID, PREDIN, 0);
    sgemm<<<GGRID(10, BB, 1), blk>>>(t1, 0, HID, mW2, 0, 10, mb2, 0, out, 0, 10, BB, 10, HID, 0);

    (void)in_sizes; (void)n_in; (void)out_size;
}

// round 4
// speedup vs baseline: 1.0021x; 1.0021x over previous
#include <cuda_runtime.h>
#include <math.h>

// ---------------- problem constants ----------------
#define NTOT   16384      // B*NPG
#define BB     32
#define NPG    512
#define DEG    16
#define KCL    64         // clusters per graph
#define ASSIGN 2048       // B*K
#define FIN    128
#define HID    256
#define EMB    256
#define GEMBD  768        // HID+HID+EMB
#define PREDIN 1536       // 2*768

// ---------------- scratch (device globals; no allocs allowed) -------------
__device__ __align__(16) float g_X   [NTOT * 512];        // sage concat input [h|hn]
__device__ __align__(16) float g_G   [NTOT * GEMBD];      // h1|h2|h3
__device__ __align__(16) float g_A12 [NTOT * 512];        // a1|a2
__device__ __align__(16) float g_S   [NTOT * KCL];        // logits -> softmax (in place)
__device__ __align__(16) float g_AS  [NTOT * KCL];
__device__ __align__(16) float g_ST  [BB * KCL * NPG];    // S^T per graph
__device__ __align__(16) float g_Hp  [BB * KCL * GEMBD];  // h_pool
__device__ __align__(16) float g_adj [BB * KCL * KCL];
__device__ __align__(16) float g_asum[BB * KCL];
__device__ __align__(16) float g_Tmp [BB * KCL * GEMBD];  // adj @ h
__device__ __align__(16) float g_XD  [BB * KCL * PREDIN]; // dense concat input
__device__ __align__(16) float g_P   [BB * KCL * GEMBD];  // p1|p2|p3
__device__ __align__(16) float g_Out [BB * PREDIN];
__device__ __align__(16) float g_t1  [BB * HID];

// ---------------- kernels ----------------

// X[n, 0:F] = h[n], X[n, F:2F] = (1/16) * sum_j h[edge_src[16n+j]]
// relies on edge_dst = repeat(arange(N), 16) (sorted, constant degree 16)
__global__ void build_sage_x(const float* __restrict__ h, int ldh, int F,
                             const int* __restrict__ esrc, float* __restrict__ X)
{
    int n = blockIdx.x;
    int f = threadIdx.x;            // blockDim == F
    __shared__ int s[DEG];
    if (f < DEG) s[f] = esrc[n * DEG + f];
    __syncthreads();
    float self = h[(long)n * ldh + f];
    float acc = 0.f;
#pragma unroll
    for (int j = 0; j < DEG; j++) acc += h[(long)s[j] * ldh + f];
    long base = (long)n * (2 * F);
    X[base + f]     = self;
    X[base + F + f] = acc * (1.0f / 16.0f);
}

// AS[n,k] = sum_j S[edge_src[16n+j], k]   (no mean)
__global__ void agg_sum64(const float* __restrict__ S, const int* __restrict__ esrc,
                          float* __restrict__ AS)
{
    int n = blockIdx.x;
    int f = threadIdx.x;            // 64
    __shared__ int s[DEG];
    if (f < DEG) s[f] = esrc[n * DEG + f];
    __syncthreads();
    float acc = 0.f;
#pragma unroll
    for (int j = 0; j < DEG; j++) acc += S[(long)s[j] * KCL + f];
    AS[(long)n * KCL + f] = acc;
}

// generic guarded SGEMM: C = A @ W + bias (opt relu), batched via blockIdx.z
__global__ void sgemm(const float* __restrict__ A, long sA, int lda,
                      const float* __restrict__ W, long sW, int ldw,
                      const float* __restrict__ bias, long sB,
                      float* __restrict__ C, long sC, int ldc,
                      int M, int Nn, int Kk, int relu)
{
    int z = blockIdx.z;
    A += (long)z * sA; W += (long)z * sW; C += (long)z * sC;
    if (bias) bias += (long)z * sB;

    __shared__ float As[8][128];
    __shared__ float Bs[8][128];
    int tid  = threadIdx.x;
    int brow = blockIdx.y * 128, bcol = blockIdx.x * 128;
    int ty = tid >> 4, tx = tid & 15;
    float acc[8][8];
#pragma unroll
    for (int i = 0; i < 8; i++)
#pragma unroll
        for (int j = 0; j < 8; j++) acc[i][j] = 0.f;

    int arow = tid >> 1;           // 0..127
    int acol = (tid & 1) * 4;      // 0 or 4

    for (int k0 = 0; k0 < Kk; k0 += 8) {
        float4 av = make_float4(0.f, 0.f, 0.f, 0.f);
        int gr = brow + arow;
        if (gr < M) av = *reinterpret_cast<const float4*>(A + (long)gr * lda + k0 + acol);
        As[acol + 0][arow] = av.x; As[acol + 1][arow] = av.y;
        As[acol + 2][arow] = av.z; As[acol + 3][arow] = av.w;
#pragma unroll
        for (int i = 0; i < 4; i++) {
            int off = tid + i * 256;
            int wr = off >> 7, wc = off & 127;
            int gc = bcol + wc;
            Bs[wr][wc] = (gc < Nn) ? W[(long)(k0 + wr) * ldw + gc] : 0.f;
        }
        __syncthreads();
#pragma unroll
        for (int kk = 0; kk < 8; kk++) {
            float ra[8], rb[8];
#pragma unroll
            for (int i = 0; i < 8; i++) ra[i] = As[kk][ty * 8 + i];
#pragma unroll
            for (int j = 0; j < 8; j++) rb[j] = Bs[kk][tx * 8 + j];
#pragma unroll
            for (int i = 0; i < 8; i++)
#pragma unroll
                for (int j = 0; j < 8; j++) acc[i][j] = fmaf(ra[i], rb[j], acc[i][j]);
        }
        __syncthreads();
    }
#pragma unroll
    for (int i = 0; i < 8; i++) {
        int r = brow + ty * 8 + i;
        if (r >= M) continue;
#pragma unroll
        for (int j = 0; j < 8; j++) {
            int c = bcol + tx * 8 + j;
            if (c >= Nn) continue;
            float v = acc[i][j] + (bias ? bias[c] : 0.f);
            if (relu) v = fmaxf(v, 0.f);
            C[(long)r * ldc + c] = v;
        }
    }
}

// Fused: S[rows of tile, 64] += relu(X3_tile @ aW3 + ab3) @ pW[512:, local 64]
// X3 = [a2 | mean a2], [N,512]. a3 never materialized in global memory.
// One block per 128-node tile (tiles never cross graphs since NPG=512).
// Dynamic smem: Ts[128*128] + Ws[128*64] + As[8*128] + Bs[8*128] = 104KB.
__global__ void fused_a3_logits(const float* __restrict__ X3,
                                const float* __restrict__ aW3,  // [512,2048]
                                const float* __restrict__ ab3,  // [2048]
                                const float* __restrict__ pW,   // [2560,2048]
                                float* __restrict__ S)          // [N,64] (+=)
{
    extern __shared__ float sm[];
    float* Ts = sm;                  // [t(128)][i(128)]  t-major
    float* Ws = Ts + 128 * 128;      // [t(128)][j(64)]
    float* As = Ws + 128 * 64;       // [k(8)][i(128)]
    float* Bs = As + 8 * 128;        // [k(8)][c(128)]

    int tid = threadIdx.x;           // 256
    int ty = tid >> 4, tx = tid & 15;
    int row0 = blockIdx.x * 128;
    int b = row0 >> 9;
    const float* pW3 = pW + (long)512 * ASSIGN + b * KCL;

    float L[8][4];
#pragma unroll
    for (int i = 0; i < 8; i++)
#pragma unroll
        for (int j = 0; j < 4; j++) L[i][j] = 0.f;

    int arow = tid >> 1;
    int acol = (tid & 1) * 4;

    for (int c = 0; c < ASSIGN; c += 128) {
        // ---- GEMM1: acc = X3_tile[128x512] @ aW3[:, c:c+128] ----
        float acc[8][8];
#pragma unroll
        for (int i = 0; i < 8; i++)
#pragma unroll
            for (int j = 0; j < 8; j++) acc[i][j] = 0.f;

        for (int k0 = 0; k0 < 512; k0 += 8) {
            float4 av = *reinterpret_cast<const float4*>(
                X3 + (long)(row0 + arow) * 512 + k0 + acol);
            As[(acol + 0) * 128 + arow] = av.x;
            As[(acol + 1) * 128 + arow] = av.y;
            As[(acol + 2) * 128 + arow] = av.z;
            As[(acol + 3) * 128 + arow] = av.w;
#pragma unroll
            for (int i = 0; i < 4; i++) {
                int off = tid + i * 256;
                int wr = off >> 7, wc = off & 127;
                Bs[wr * 128 + wc] = aW3[(long)(k0 + wr) * ASSIGN + c + wc];
            }
            __syncthreads();
#pragma unroll
            for (int kk = 0; kk < 8; kk++) {
                float ra[8], rb[8];
#pragma unroll
                for (int i = 0; i < 8; i++) ra[i] = As[kk * 128 + ty * 8 + i];
#pragma unroll
                for (int j = 0; j < 8; j++) rb[j] = Bs[kk * 128 + tx * 8 + j];
#pragma unroll
                for (int i = 0; i < 8; i++)
#pragma unroll
                    for (int j = 0; j < 8; j++) acc[i][j] = fmaf(ra[i], rb[j], acc[i][j]);
            }
            __syncthreads();
        }
        // bias + relu -> Ts (t-major), and stage pW3 chunk -> Ws
#pragma unroll
        for (int jj = 0; jj < 8; jj++) {
            int t = tx * 8 + jj;
            float bb = ab3[c + t];
#pragma unroll
            for (int ii = 0; ii < 8; ii++) {
                Ts[t * 128 + ty * 8 + ii] = fmaxf(acc[ii][jj] + bb, 0.f);
            }
        }
        for (int idx = tid; idx < 128 * 64; idx += 256) {
            int t = idx >> 6, j = idx & 63;
            Ws[idx] = pW3[(long)(c + t) * ASSIGN + j];
        }
        __syncthreads();
        // ---- GEMM2: L += Ts^T-slice @ Ws ----
#pragma unroll 4
        for (int t = 0; t < 128; t++) {
            float rb[4];
#pragma unroll
            for (int j = 0; j < 4; j++) rb[j] = Ws[t * 64 + tx * 4 + j];
            float ra[8];
#pragma unroll
            for (int i = 0; i < 8; i++) ra[i] = Ts[t * 128 + ty * 8 + i];
#pragma unroll
            for (int i = 0; i < 8; i++)
#pragma unroll
                for (int j = 0; j < 4; j++) L[i][j] = fmaf(ra[i], rb[j], L[i][j]);
        }
        __syncthreads();   // protect Ts/Ws before next chunk rewrites
    }
#pragma unroll
    for (int i = 0; i < 8; i++) {
        long r = row0 + ty * 8 + i;
#pragma unroll
        for (int j = 0; j < 4; j++)
            S[r * KCL + tx * 4 + j] += L[i][j];
    }
}

// masked softmax over the local 64 columns (in place)
__global__ void softmax64(float* __restrict__ S)
{
    int n = blockIdx.x, c = threadIdx.x;  // 64 threads
    __shared__ float red[64];
    float v = S[(long)n * KCL + c];
    red[c] = v; __syncthreads();
    for (int s = 32; s > 0; s >>= 1) { if (c < s) red[c] = fmaxf(red[c], red[c + s]); __syncthreads(); }
    float m = red[0]; __syncthreads();
    float e = expf(v - m);
    red[c] = e; __syncthreads();
    for (int s = 32; s > 0; s >>= 1) { if (c < s) red[c] += red[c + s]; __syncthreads(); }
    float sum = red[0];
    S[(long)n * KCL + c] = e / sum;
}

// ST[b,k,n_local] = S[b*512+n_local, k]
__global__ void transS(const float* __restrict__ S, float* __restrict__ ST)
{
    int n = blockIdx.x, k = threadIdx.x;  // 64
    int b = n >> 9, nn = n & 511;
    ST[((long)(b * KCL + k)) * NPG + nn] = S[(long)n * KCL + k];
}

__global__ void adjsum_k(const float* __restrict__ adj, float* __restrict__ asum)
{
    int i = blockIdx.x * blockDim.x + threadIdx.x;
    if (i < BB * KCL) {
        float s = 0.f;
#pragma unroll 8
        for (int j = 0; j < KCL; j++) s += adj[(long)i * KCL + j];
        asum[i] = s + 1e-9f;
    }
}

// XD[i, 0:d] = h[i], XD[i, d:2d] = tmp[i] / asum[i]
__global__ void dense_concat(const float* __restrict__ h, int ldh,
                             const float* __restrict__ tmp, int d,
                             const float* __restrict__ asum, float* __restrict__ XD)
{
    int i = blockIdx.x, t = threadIdx.x;  // blockDim == d
    float inv = 1.0f / asum[i];
    long base = (long)i * (2 * d);
    XD[base + t]     = h[(long)i * ldh + t];
    XD[base + d + t] = tmp[(long)i * d + t] * inv;
}

__global__ void maxpool_k(const float* __restrict__ Xp, int rows, int ld, int d,
                          float* __restrict__ out, int ldo, int off)
{
    int b = blockIdx.x;
    int j = blockIdx.y * blockDim.x + threadIdx.x;
    if (j >= d) return;
    const float* p = Xp + (long)b * rows * ld + j;
    float m = -3.4e38f;
    for (int r = 0; r < rows; r++) m = fmaxf(m, p[(long)r * ld]);
    out[(long)b * ldo + off + j] = m;
}

// ---------------- launch ----------------
extern "C" void kernel_launch(void* const* d_in, const int* in_sizes, int n_in,
                              void* d_out, int out_size)
{
    const float* feat = (const float*)d_in[0];
    const int*   esrc = (const int*)d_in[1];
    // d_in[2] = edge_dst (structure known: repeat(arange(N),16))
    const float *W1 = (const float*)d_in[3],  *b1  = (const float*)d_in[4];
    const float *W2 = (const float*)d_in[5],  *b2  = (const float*)d_in[6];
    const float *W3 = (const float*)d_in[7],  *b3  = (const float*)d_in[8];
    const float *aW1= (const float*)d_in[9],  *ab1 = (const float*)d_in[10];
    const float *aW2= (const float*)d_in[11], *ab2 = (const float*)d_in[12];
    const float *aW3= (const float*)d_in[13], *ab3 = (const float*)d_in[14];
    const float *pW = (const float*)d_in[15], *pb  = (const float*)d_in[16];
    const float *qW1= (const float*)d_in[17], *qb1 = (const float*)d_in[18];
    const float *qW2= (const float*)d_in[19], *qb2 = (const float*)d_in[20];
    const float *qW3= (const float*)d_in[21], *qb3 = (const float*)d_in[22];
    const float *mW1= (const float*)d_in[23], *mb1 = (const float*)d_in[24];
    const float *mW2= (const float*)d_in[25], *mb2 = (const float*)d_in[26];
    float* out = (float*)d_out;

    void *p;
    cudaGetSymbolAddress(&p, g_X);    float* X   = (float*)p;
    cudaGetSymbolAddress(&p, g_G);    float* G   = (float*)p;
    cudaGetSymbolAddress(&p, g_A12);  float* A12 = (float*)p;
    cudaGetSymbolAddress(&p, g_S);    float* S   = (float*)p;
    cudaGetSymbolAddress(&p, g_AS);   float* AS  = (float*)p;
    cudaGetSymbolAddress(&p, g_ST);   float* ST  = (float*)p;
    cudaGetSymbolAddress(&p, g_Hp);   float* Hp  = (float*)p;
    cudaGetSymbolAddress(&p, g_adj);  float* adj = (float*)p;
    cudaGetSymbolAddress(&p, g_asum); float* asum= (float*)p;
    cudaGetSymbolAddress(&p, g_Tmp);  float* Tmp = (float*)p;
    cudaGetSymbolAddress(&p, g_XD);   float* XD  = (float*)p;
    cudaGetSymbolAddress(&p, g_P);    float* P   = (float*)p;
    cudaGetSymbolAddress(&p, g_Out);  float* Out = (float*)p;
    cudaGetSymbolAddress(&p, g_t1);   float* t1  = (float*)p;

    const int FUSED_SMEM = (128 * 128 + 128 * 64 + 8 * 128 + 8 * 128) * 4;  // 104KB
    cudaFuncSetAttribute(fused_a3_logits, cudaFuncAttributeMaxDynamicSharedMemorySize, FUSED_SMEM);

    dim3 blk(256);
    #define GGRID(Nn, M, Z) dim3(((Nn)+127)/128, ((M)+127)/128, (Z))

    // ---- shared first sage input (feat) ----
    build_sage_x<<<NTOT, FIN>>>(feat, FIN, FIN, esrc, X);
    // h1 = relu(X @ W1 + b1) ; a1 = relu(X @ aW1 + ab1)
    sgemm<<<GGRID(HID, NTOT, 1), blk>>>(X, 0, 2*FIN, W1, 0, HID, b1, 0, G,      0, GEMBD, NTOT, HID, 2*FIN, 1);
    sgemm<<<GGRID(HID, NTOT, 1), blk>>>(X, 0, 2*FIN, aW1,0, HID, ab1,0, A12,    0, 512,   NTOT, HID, 2*FIN, 1);
    // h2
    build_sage_x<<<NTOT, HID>>>(G, GEMBD, HID, esrc, X);
    sgemm<<<GGRID(HID, NTOT, 1), blk>>>(X, 0, 2*HID, W2, 0, HID, b2, 0, G+HID,  0, GEMBD, NTOT, HID, 2*HID, 1);
    // a2
    build_sage_x<<<NTOT, HID>>>(A12, 512, HID, esrc, X);
    sgemm<<<GGRID(HID, NTOT, 1), blk>>>(X, 0, 2*HID, aW2,0, HID, ab2,0, A12+HID,0, 512,   NTOT, HID, 2*HID, 1);
    // h3 (no relu)
    build_sage_x<<<NTOT, HID>>>(G+HID, GEMBD, HID, esrc, X);
    sgemm<<<GGRID(EMB, NTOT, 1), blk>>>(X, 0, 2*HID, W3, 0, EMB, b3, 0, G+2*HID,0, GEMBD, NTOT, EMB, 2*HID, 0);

    // ---- logits: [a1|a2] part (batched local-64-column slice of pW) ----
    sgemm<<<GGRID(KCL, NPG, BB), blk>>>(A12, (long)NPG*512, 512,
                                        pW, KCL, ASSIGN, pb, KCL,
                                        S, (long)NPG*KCL, KCL, NPG, KCL, 512, 0);
    // ---- a3 part, fused (a3 never hits DRAM) ----
    build_sage_x<<<NTOT, HID>>>(A12+HID, 512, HID, esrc, X);
    fused_a3_logits<<<NTOT/128, 256, FUSED_SMEM>>>(X, aW3, ab3, pW, S);
    softmax64<<<NTOT, KCL>>>(S);

    // ---- pooling ----
    agg_sum64<<<NTOT, KCL>>>(S, esrc, AS);
    transS<<<NTOT, KCL>>>(S, ST);
    // h_pool[b] = S[b]^T @ G[b]   (64 x 768)
    sgemm<<<GGRID(GEMBD, KCL, BB), blk>>>(ST, (long)KCL*NPG, NPG,
                                          G, (long)NPG*GEMBD, GEMBD, (const float*)0, 0,
                                          Hp, (long)KCL*GEMBD, GEMBD, KCL, GEMBD, NPG, 0);
    // adj[b] = S[b]^T @ AS[b]     (64 x 64)
    sgemm<<<GGRID(KCL, KCL, BB), blk>>>(ST, (long)KCL*NPG, NPG,
                                        AS, (long)NPG*KCL, KCL, (const float*)0, 0,
                                        adj, (long)KCL*KCL, KCL, KCL, KCL, NPG, 0);
    adjsum_k<<<(BB*KCL+255)/256, 256>>>(adj, asum);

    // ---- dense sage layer 1 (input 768 -> 256, relu) ----
    sgemm<<<GGRID(GEMBD, KCL, BB), blk>>>(adj, (long)KCL*KCL, KCL,
                                          Hp, (long)KCL*GEMBD, GEMBD, (const float*)0, 0,
                                          Tmp, (long)KCL*GEMBD, GEMBD, KCL, GEMBD, KCL, 0);
    dense_concat<<<BB*KCL, GEMBD>>>(Hp, GEMBD, Tmp, GEMBD, asum, XD);
    sgemm<<<GGRID(HID, BB*KCL, 1), blk>>>(XD, 0, PREDIN, qW1, 0, HID, qb1, 0, P, 0, GEMBD, BB*KCL, HID, PREDIN, 1);
    // layer 2 (256 -> 256, relu)
    sgemm<<<GGRID(HID, KCL, BB), blk>>>(adj, (long)KCL*KCL, KCL,
                                        P, (long)KCL*GEMBD, GEMBD, (const float*)0, 0,
                                        Tmp, (long)KCL*HID, HID, KCL, HID, KCL, 0);
    dense_concat<<<BB*KCL, HID>>>(P, GEMBD, Tmp, HID, asum, XD);
    sgemm<<<GGRID(HID, BB*KCL, 1), blk>>>(XD, 0, 2*HID, qW2, 0, HID, qb2, 0, P+HID, 0, GEMBD, BB*KCL, HID, 2*HID, 1);
    // layer 3 (256 -> 256, no relu)
    sgemm<<<GGRID(HID, KCL, BB), blk>>>(adj, (long)KCL*KCL, KCL,
                                        P+HID, (long)KCL*GEMBD, GEMBD, (const float*)0, 0,
                                        Tmp, (long)KCL*HID, HID, KCL, HID, KCL, 0);
    dense_concat<<<BB*KCL, HID>>>(P+HID, GEMBD, Tmp, HID, asum, XD);
    sgemm<<<GGRID(HID, BB*KCL, 1), blk>>>(XD, 0, 2*HID, qW3, 0, HID, qb3, 0, P+2*HID, 0, GEMBD, BB*KCL, HID, 2*HID, 0);

    // ---- readouts ----
    maxpool_k<<<dim3(BB, (GEMBD+255)/256), 256>>>(G, NPG, GEMBD, GEMBD, Out, PREDIN, 0);
    maxpool_k<<<dim3(BB, (GEMBD+255)/256), 256>>>(P, KCL, GEMBD, GEMBD, Out, PREDIN, GEMBD);

    // ---- pred MLP ----
    sgemm<<<GGRID(HID, BB, 1), blk>>>(Out, 0, PREDIN, mW1, 0, HID, mb1, 0, t1, 0, HID, BB, HID, PREDIN, 0);
    sgemm<<<GGRID(10, BB, 1), blk>>>(t1, 0, HID, mW2, 0, 10, mb2, 0, out, 0, 10, BB, 10, HID, 0);

    (void)in_sizes; (void)n_in; (void)out_size;
}

// round 5
// speedup vs baseline: 1.0027x; 1.0006x over previous
#include <cuda_runtime.h>
#include <math.h>

// ---------------- problem constants ----------------
#define NTOT   16384      // B*NPG
#define BB     32
#define NPG    512
#define DEG    16
#define KCL    64         // clusters per graph
#define ASSIGN 2048       // B*K
#define FIN    128
#define HID    256
#define EMB    256
#define GEMBD  768        // HID+HID+EMB
#define PREDIN 1536       // 2*768

// ---------------- scratch (device globals; no allocs allowed) -------------
__device__ __align__(16) float g_X   [NTOT * 512];        // sage concat input [h|hn]
__device__ __align__(16) float g_G   [NTOT * GEMBD];      // h1|h2|h3
__device__ __align__(16) float g_A12 [NTOT * 512];        // a1|a2
__device__ __align__(16) float g_S   [NTOT * KCL];        // logits -> softmax (in place)
__device__ __align__(16) float g_AS  [NTOT * KCL];
__device__ __align__(16) float g_ST  [BB * KCL * NPG];    // S^T per graph
__device__ __align__(16) float g_Hp  [BB * KCL * GEMBD];  // h_pool
__device__ __align__(16) float g_adj [BB * KCL * KCL];
__device__ __align__(16) float g_asum[BB * KCL];
__device__ __align__(16) float g_Tmp [BB * KCL * GEMBD];  // adj @ h
__device__ __align__(16) float g_XD  [BB * KCL * PREDIN]; // dense concat input
__device__ __align__(16) float g_P   [BB * KCL * GEMBD];  // p1|p2|p3
__device__ __align__(16) float g_Out [BB * PREDIN];
__device__ __align__(16) float g_t1  [BB * HID];

// ---------------- kernels ----------------

// X[n, 0:F] = h[n], X[n, F:2F] = (1/16) * sum_j h[edge_src[16n+j]]
// relies on edge_dst = repeat(arange(N), 16) (sorted, constant degree 16)
__global__ void build_sage_x(const float* __restrict__ h, int ldh, int F,
                             const int* __restrict__ esrc, float* __restrict__ X)
{
    int n = blockIdx.x;
    int f = threadIdx.x;            // blockDim == F
    __shared__ int s[DEG];
    if (f < DEG) s[f] = esrc[n * DEG + f];
    __syncthreads();
    float self = h[(long)n * ldh + f];
    float acc = 0.f;
#pragma unroll
    for (int j = 0; j < DEG; j++) acc += h[(long)s[j] * ldh + f];
    long base = (long)n * (2 * F);
    X[base + f]     = self;
    X[base + F + f] = acc * (1.0f / 16.0f);
}

// AS[n,k] = sum_j S[edge_src[16n+j], k]   (no mean)
__global__ void agg_sum64(const float* __restrict__ S, const int* __restrict__ esrc,
                          float* __restrict__ AS)
{
    int n = blockIdx.x;
    int f = threadIdx.x;            // 64
    __shared__ int s[DEG];
    if (f < DEG) s[f] = esrc[n * DEG + f];
    __syncthreads();
    float acc = 0.f;
#pragma unroll
    for (int j = 0; j < DEG; j++) acc += S[(long)s[j] * KCL + f];
    AS[(long)n * KCL + f] = acc;
}

// generic guarded SGEMM: C = A @ W + bias (opt relu), batched via blockIdx.z
__global__ void sgemm(const float* __restrict__ A, long sA, int lda,
                      const float* __restrict__ W, long sW, int ldw,
                      const float* __restrict__ bias, long sB,
                      float* __restrict__ C, long sC, int ldc,
                      int M, int Nn, int Kk, int relu)
{
    int z = blockIdx.z;
    A += (long)z * sA; W += (long)z * sW; C += (long)z * sC;
    if (bias) bias += (long)z * sB;

    __shared__ float As[8][128];
    __shared__ float Bs[8][128];
    int tid  = threadIdx.x;
    int brow = blockIdx.y * 128, bcol = blockIdx.x * 128;
    int ty = tid >> 4, tx = tid & 15;
    float acc[8][8];
#pragma unroll
    for (int i = 0; i < 8; i++)
#pragma unroll
        for (int j = 0; j < 8; j++) acc[i][j] = 0.f;

    int arow = tid >> 1;           // 0..127
    int acol = (tid & 1) * 4;      // 0 or 4

    for (int k0 = 0; k0 < Kk; k0 += 8) {
        float4 av = make_float4(0.f, 0.f, 0.f, 0.f);
        int gr = brow + arow;
        if (gr < M) av = *reinterpret_cast<const float4*>(A + (long)gr * lda + k0 + acol);
        As[acol + 0][arow] = av.x; As[acol + 1][arow] = av.y;
        As[acol + 2][arow] = av.z; As[acol + 3][arow] = av.w;
#pragma unroll
        for (int i = 0; i < 4; i++) {
            int off = tid + i * 256;
            int wr = off >> 7, wc = off & 127;
            int gc = bcol + wc;
            Bs[wr][wc] = (gc < Nn) ? W[(long)(k0 + wr) * ldw + gc] : 0.f;
        }
        __syncthreads();
#pragma unroll
        for (int kk = 0; kk < 8; kk++) {
            float ra[8], rb[8];
#pragma unroll
            for (int i = 0; i < 8; i++) ra[i] = As[kk][ty * 8 + i];
#pragma unroll
            for (int j = 0; j < 8; j++) rb[j] = Bs[kk][tx * 8 + j];
#pragma unroll
            for (int i = 0; i < 8; i++)
#pragma unroll
                for (int j = 0; j < 8; j++) acc[i][j] = fmaf(ra[i], rb[j], acc[i][j]);
        }
        __syncthreads();
    }
#pragma unroll
    for (int i = 0; i < 8; i++) {
        int r = brow + ty * 8 + i;
        if (r >= M) continue;
#pragma unroll
        for (int j = 0; j < 8; j++) {
            int c = bcol + tx * 8 + j;
            if (c >= Nn) continue;
            float v = acc[i][j] + (bias ? bias[c] : 0.f);
            if (relu) v = fmaxf(v, 0.f);
            C[(long)r * ldc + c] = v;
        }
    }
}

// Fused: S[rows of tile, 64] += relu(X3_tile @ aW3 + ab3) @ pW[512:, local 64]
// X3 = [a2 | mean a2], [N,512]. a3 never materialized in global memory.
// One block per 128-node tile (tiles never cross graphs since NPG=512).
// Dynamic smem: Ts[128*128] + Ws[128*64] + As[8*128] + Bs[8*128] = 104KB.
__global__ void fused_a3_logits(const float* __restrict__ X3,
                                const float* __restrict__ aW3,  // [512,2048]
                                const float* __restrict__ ab3,  // [2048]
                                const float* __restrict__ pW,   // [2560,2048]
                                float* __restrict__ S)          // [N,64] (+=)
{
    extern __shared__ float sm[];
    float* Ts = sm;                  // [t(128)][i(128)]  t-major
    float* Ws = Ts + 128 * 128;      // [t(128)][j(64)]
    float* As = Ws + 128 * 64;       // [k(8)][i(128)]
    float* Bs = As + 8 * 128;        // [k(8)][c(128)]

    int tid = threadIdx.x;           // 256
    int ty = tid >> 4, tx = tid & 15;
    int row0 = blockIdx.x * 128;
    int b = row0 >> 9;
    const float* pW3 = pW + (long)512 * ASSIGN + b * KCL;

    float L[8][4];
#pragma unroll
    for (int i = 0; i < 8; i++)
#pragma unroll
        for (int j = 0; j < 4; j++) L[i][j] = 0.f;

    int arow = tid >> 1;
    int acol = (tid & 1) * 4;

    for (int c = 0; c < ASSIGN; c += 128) {
        // ---- GEMM1: acc = X3_tile[128x512] @ aW3[:, c:c+128] ----
        float acc[8][8];
#pragma unroll
        for (int i = 0; i < 8; i++)
#pragma unroll
            for (int j = 0; j < 8; j++) acc[i][j] = 0.f;

        for (int k0 = 0; k0 < 512; k0 += 8) {
            float4 av = *reinterpret_cast<const float4*>(
                X3 + (long)(row0 + arow) * 512 + k0 + acol);
            As[(acol + 0) * 128 + arow] = av.x;
            As[(acol + 1) * 128 + arow] = av.y;
            As[(acol + 2) * 128 + arow] = av.z;
            As[(acol + 3) * 128 + arow] = av.w;
#pragma unroll
            for (int i = 0; i < 4; i++) {
                int off = tid + i * 256;
                int wr = off >> 7, wc = off & 127;
                Bs[wr * 128 + wc] = aW3[(long)(k0 + wr) * ASSIGN + c + wc];
            }
            __syncthreads();
#pragma unroll
            for (int kk = 0; kk < 8; kk++) {
                float ra[8], rb[8];
#pragma unroll
                for (int i = 0; i < 8; i++) ra[i] = As[kk * 128 + ty * 8 + i];
#pragma unroll
                for (int j = 0; j < 8; j++) rb[j] = Bs[kk * 128 + tx * 8 + j];
#pragma unroll
                for (int i = 0; i < 8; i++)
#pragma unroll
                    for (int j = 0; j < 8; j++) acc[i][j] = fmaf(ra[i], rb[j], acc[i][j]);
            }
            __syncthreads();
        }
        // bias + relu -> Ts (t-major), and stage pW3 chunk -> Ws
#pragma unroll
        for (int jj = 0; jj < 8; jj++) {
            int t = tx * 8 + jj;
            float bb = ab3[c + t];
#pragma unroll
            for (int ii = 0; ii < 8; ii++) {
                Ts[t * 128 + ty * 8 + ii] = fmaxf(acc[ii][jj] + bb, 0.f);
            }
        }
        for (int idx = tid; idx < 128 * 64; idx += 256) {
            int t = idx >> 6, j = idx & 63;
            Ws[idx] = pW3[(long)(c + t) * ASSIGN + j];
        }
        __syncthreads();
        // ---- GEMM2: L += Ts^T-slice @ Ws ----
#pragma unroll 4
        for (int t = 0; t < 128; t++) {
            float rb[4];
#pragma unroll
            for (int j = 0; j < 4; j++) rb[j] = Ws[t * 64 + tx * 4 + j];
            float ra[8];
#pragma unroll
            for (int i = 0; i < 8; i++) ra[i] = Ts[t * 128 + ty * 8 + i];
#pragma unroll
            for (int i = 0; i < 8; i++)
#pragma unroll
                for (int j = 0; j < 4; j++) L[i][j] = fmaf(ra[i], rb[j], L[i][j]);
        }
        __syncthreads();   // protect Ts/Ws before next chunk rewrites
    }
#pragma unroll
    for (int i = 0; i < 8; i++) {
        long r = row0 + ty * 8 + i;
#pragma unroll
        for (int j = 0; j < 4; j++)
            S[r * KCL + tx * 4 + j] += L[i][j];
    }
}

// masked softmax over the local 64 columns (in place)
__global__ void softmax64(float* __restrict__ S)
{
    int n = blockIdx.x, c = threadIdx.x;  // 64 threads
    __shared__ float red[64];
    float v = S[(long)n * KCL + c];
    red[c] = v; __syncthreads();
    for (int s = 32; s > 0; s >>= 1) { if (c < s) red[c] = fmaxf(red[c], red[c + s]); __syncthreads(); }
    float m = red[0]; __syncthreads();
    float e = expf(v - m);
    red[c] = e; __syncthreads();
    for (int s = 32; s > 0; s >>= 1) { if (c < s) red[c] += red[c + s]; __syncthreads(); }
    float sum = red[0];
    S[(long)n * KCL + c] = e / sum;
}

// ST[b,k,n_local] = S[b*512+n_local, k]
__global__ void transS(const float* __restrict__ S, float* __restrict__ ST)
{
    int n = blockIdx.x, k = threadIdx.x;  // 64
    int b = n >> 9, nn = n & 511;
    ST[((long)(b * KCL + k)) * NPG + nn] = S[(long)n * KCL + k];
}

__global__ void adjsum_k(const float* __restrict__ adj, float* __restrict__ asum)
{
    int i = blockIdx.x * blockDim.x + threadIdx.x;
    if (i < BB * KCL) {
        float s = 0.f;
#pragma unroll 8
        for (int j = 0; j < KCL; j++) s += adj[(long)i * KCL + j];
        asum[i] = s + 1e-9f;
    }
}

// XD[i, 0:d] = h[i], XD[i, d:2d] = tmp[i] / asum[i]
__global__ void dense_concat(const float* __restrict__ h, int ldh,
                             const float* __restrict__ tmp, int d,
                             const float* __restrict__ asum, float* __restrict__ XD)
{
    int i = blockIdx.x, t = threadIdx.x;  // blockDim == d
    float inv = 1.0f / asum[i];
    long base = (long)i * (2 * d);
    XD[base + t]     = h[(long)i * ldh + t];
    XD[base + d + t] = tmp[(long)i * d + t] * inv;
}

__global__ void maxpool_k(const float* __restrict__ Xp, int rows, int ld, int d,
                          float* __restrict__ out, int ldo, int off)
{
    int b = blockIdx.x;
    int j = blockIdx.y * blockDim.x + threadIdx.x;
    if (j >= d) return;
    const float* p = Xp + (long)b * rows * ld + j;
    float m = -3.4e38f;
    for (int r = 0; r < rows; r++) m = fmaxf(m, p[(long)r * ld]);
    out[(long)b * ldo + off + j] = m;
}

// ---------------- launch ----------------
extern "C" void kernel_launch(void* const* d_in, const int* in_sizes, int n_in,
                              void* d_out, int out_size)
{
    const float* feat = (const float*)d_in[0];
    const int*   esrc = (const int*)d_in[1];
    // d_in[2] = edge_dst (structure known: repeat(arange(N),16))
    const float *W1 = (const float*)d_in[3],  *b1  = (const float*)d_in[4];
    const float *W2 = (const float*)d_in[5],  *b2  = (const float*)d_in[6];
    const float *W3 = (const float*)d_in[7],  *b3  = (const float*)d_in[8];
    const float *aW1= (const float*)d_in[9],  *ab1 = (const float*)d_in[10];
    const float *aW2= (const float*)d_in[11], *ab2 = (const float*)d_in[12];
    const float *aW3= (const float*)d_in[13], *ab3 = (const float*)d_in[14];
    const float *pW = (const float*)d_in[15], *pb  = (const float*)d_in[16];
    const float *qW1= (const float*)d_in[17], *qb1 = (const float*)d_in[18];
    const float *qW2= (const float*)d_in[19], *qb2 = (const float*)d_in[20];
    const float *qW3= (const float*)d_in[21], *qb3 = (const float*)d_in[22];
    const float *mW1= (const float*)d_in[23], *mb1 = (const float*)d_in[24];
    const float *mW2= (const float*)d_in[25], *mb2 = (const float*)d_in[26];
    float* out = (float*)d_out;

    void *p;
    cudaGetSymbolAddress(&p, g_X);    float* X   = (float*)p;
    cudaGetSymbolAddress(&p, g_G);    float* G   = (float*)p;
    cudaGetSymbolAddress(&p, g_A12);  float* A12 = (float*)p;
    cudaGetSymbolAddress(&p, g_S);    float* S   = (float*)p;
    cudaGetSymbolAddress(&p, g_AS);   float* AS  = (float*)p;
    cudaGetSymbolAddress(&p, g_ST);   float* ST  = (float*)p;
    cudaGetSymbolAddress(&p, g_Hp);   float* Hp  = (float*)p;
    cudaGetSymbolAddress(&p, g_adj);  float* adj = (float*)p;
    cudaGetSymbolAddress(&p, g_asum); float* asum= (float*)p;
    cudaGetSymbolAddress(&p, g_Tmp);  float* Tmp = (float*)p;
    cudaGetSymbolAddress(&p, g_XD);   float* XD  = (float*)p;
    cudaGetSymbolAddress(&p, g_P);    float* P   = (float*)p;
    cudaGetSymbolAddress(&p, g_Out);  float* Out = (float*)p;
    cudaGetSymbolAddress(&p, g_t1);   float* t1  = (float*)p;

    const int FUSED_SMEM = (128 * 128 + 128 * 64 + 8 * 128 + 8 * 128) * 4;  // 104KB
    cudaFuncSetAttribute(fused_a3_logits, cudaFuncAttributeMaxDynamicSharedMemorySize, FUSED_SMEM);

    dim3 blk(256);
    #define GGRID(Nn, M, Z) dim3(((Nn)+127)/128, ((M)+127)/128, (Z))

    // ---- shared first sage input (feat) ----
    build_sage_x<<<NTOT, FIN>>>(feat, FIN, FIN, esrc, X);
    // h1 = relu(X @ W1 + b1) ; a1 = relu(X @ aW1 + ab1)
    sgemm<<<GGRID(HID, NTOT, 1), blk>>>(X, 0, 2*FIN, W1, 0, HID, b1, 0, G,      0, GEMBD, NTOT, HID, 2*FIN, 1);
    sgemm<<<GGRID(HID, NTOT, 1), blk>>>(X, 0, 2*FIN, aW1,0, HID, ab1,0, A12,    0, 512,   NTOT, HID, 2*FIN, 1);
    // h2
    build_sage_x<<<NTOT, HID>>>(G, GEMBD, HID, esrc, X);
    sgemm<<<GGRID(HID, NTOT, 1), blk>>>(X, 0, 2*HID, W2, 0, HID, b2, 0, G+HID,  0, GEMBD, NTOT, HID, 2*HID, 1);
    // a2
    build_sage_x<<<NTOT, HID>>>(A12, 512, HID, esrc, X);
    sgemm<<<GGRID(HID, NTOT, 1), blk>>>(X, 0, 2*HID, aW2,0, HID, ab2,0, A12+HID,0, 512,   NTOT, HID, 2*HID, 1);
    // h3 (no relu)
    build_sage_x<<<NTOT, HID>>>(G+HID, GEMBD, HID, esrc, X);
    sgemm<<<GGRID(EMB, NTOT, 1), blk>>>(X, 0, 2*HID, W3, 0, EMB, b3, 0, G+2*HID,0, GEMBD, NTOT, EMB, 2*HID, 0);

    // ---- logits: [a1|a2] part (batched local-64-column slice of pW) ----
    sgemm<<<GGRID(KCL, NPG, BB), blk>>>(A12, (long)NPG*512, 512,
                                        pW, KCL, ASSIGN, pb, KCL,
                                        S, (long)NPG*KCL, KCL, NPG, KCL, 512, 0);
    // ---- a3 part, fused (a3 never hits DRAM) ----
    build_sage_x<<<NTOT, HID>>>(A12+HID, 512, HID, esrc, X);
    fused_a3_logits<<<NTOT/128, 256, FUSED_SMEM>>>(X, aW3, ab3, pW, S);
    softmax64<<<NTOT, KCL>>>(S);

    // ---- pooling ----
    agg_sum64<<<NTOT, KCL>>>(S, esrc, AS);
    transS<<<NTOT, KCL>>>(S, ST);
    // h_pool[b] = S[b]^T @ G[b]   (64 x 768)
    sgemm<<<GGRID(GEMBD, KCL, BB), blk>>>(ST, (long)KCL*NPG, NPG,
                                          G, (long)NPG*GEMBD, GEMBD, (const float*)0, 0,
                                          Hp, (long)KCL*GEMBD, GEMBD, KCL, GEMBD, NPG, 0);
    // adj[b] = S[b]^T @ AS[b]     (64 x 64)
    sgemm<<<GGRID(KCL, KCL, BB), blk>>>(ST, (long)KCL*NPG, NPG,
                                        AS, (long)NPG*KCL, KCL, (const float*)0, 0,
                                        adj, (long)KCL*KCL, KCL, KCL, KCL, NPG, 0);
    adjsum_k<<<(BB*KCL+255)/256, 256>>>(adj, asum);

    // ---- dense sage layer 1 (input 768 -> 256, relu) ----
    sgemm<<<GGRID(GEMBD, KCL, BB), blk>>>(adj, (long)KCL*KCL, KCL,
                                          Hp, (long)KCL*GEMBD, GEMBD, (const float*)0, 0,
                                          Tmp, (long)KCL*GEMBD, GEMBD, KCL, GEMBD, KCL, 0);
    dense_concat<<<BB*KCL, GEMBD>>>(Hp, GEMBD, Tmp, GEMBD, asum, XD);
    sgemm<<<GGRID(HID, BB*KCL, 1), blk>>>(XD, 0, PREDIN, qW1, 0, HID, qb1, 0, P, 0, GEMBD, BB*KCL, HID, PREDIN, 1);
    // layer 2 (256 -> 256, relu)
    sgemm<<<GGRID(HID, KCL, BB), blk>>>(adj, (long)KCL*KCL, KCL,
                                        P, (long)KCL*GEMBD, GEMBD, (const float*)0, 0,
                                        Tmp, (long)KCL*HID, HID, KCL, HID, KCL, 0);
    dense_concat<<<BB*KCL, HID>>>(P, GEMBD, Tmp, HID, asum, XD);
    sgemm<<<GGRID(HID, BB*KCL, 1), blk>>>(XD, 0, 2*HID, qW2, 0, HID, qb2, 0, P+HID, 0, GEMBD, BB*KCL, HID, 2*HID, 1);
    // layer 3 (256 -> 256, no relu)
    sgemm<<<GGRID(HID, KCL, BB), blk>>>(adj, (long)KCL*KCL, KCL,
                                        P+HID, (long)KCL*GEMBD, GEMBD, (const float*)0, 0,
                                        Tmp, (long)KCL*HID, HID, KCL, HID, KCL, 0);
    dense_concat<<<BB*KCL, HID>>>(P+HID, GEMBD, Tmp, HID, asum, XD);
    sgemm<<<GGRID(HID, BB*KCL, 1), blk>>>(XD, 0, 2*HID, qW3, 0, HID, qb3, 0, P+2*HID, 0, GEMBD, BB*KCL, HID, 2*HID, 0);

    // ---- readouts ----
    maxpool_k<<<dim3(BB, (GEMBD+255)/256), 256>>>(G, NPG, GEMBD, GEMBD, Out, PREDIN, 0);
    maxpool_k<<<dim3(BB, (GEMBD+255)/256), 256>>>(P, KCL, GEMBD, GEMBD, Out, PREDIN, GEMBD);

    // ---- pred MLP ----
    sgemm<<<GGRID(HID, BB, 1), blk>>>(Out, 0, PREDIN, mW1, 0, HID, mb1, 0, t1, 0, HID, BB, HID, PREDIN, 0);
    sgemm<<<GGRID(10, BB, 1), blk>>>(t1, 0, HID, mW2, 0, 10, mb2, 0, out, 0, 10, BB, 10, HID, 0);

    (void)in_sizes; (void)n_in; (void)out_size;
}